// round 8
// baseline (speedup 1.0000x reference)
#include <cuda_runtime.h>
#include <cuda_fp16.h>
#include <math.h>
#include <stdint.h>

#define NN 50000
#define NE 800000
#define IND 256
#define F1 256          // HEADS*HID
#define HEADS 4
#define HID 64
#define DOUT 64
#define NEG 0.2f

// ---------------- scratch (device globals: no allocation allowed) ----------------
__device__ __half g_xh[NN * IND];       // x in fp16 (GEMM1 A)
__device__ __half g_w1t[F1 * IND];      // W1^T fp16: [n][k]
__device__ __half g_w2t[DOUT * F1];     // W2^T fp16: [n][k]
__device__ __half g_feat1h[NN * F1];    // x @ W1 (fp16)
__device__ float  g_el1[NN * HEADS];
__device__ float  g_er1[NN * HEADS];
__device__ __half g_h1h[NN * F1];       // layer-1 output after elu (fp16, GEMM2 A)
__device__ __half g_feat2h[NN * DOUT];  // h1 @ W2 (fp16)
__device__ float  g_el2[NN];
__device__ float  g_er2[NN];
// CSR by dst
__device__ int g_cnt[NN];               // statically zero; re-zeroed by scan_kernel each run
__device__ int g_off[NN + 1];
__device__ int g_cur[NN];
__device__ int g_csr_src[NE];

__device__ __forceinline__ float lrelu(float v) { return v > 0.f ? v : NEG * v; }

// ---------------- cp.async helpers ----------------
__device__ __forceinline__ void cp_async16(void* smem_ptr, const void* gmem, int src_sz) {
    uint32_t s = (uint32_t)__cvta_generic_to_shared(smem_ptr);
    asm volatile("cp.async.cg.shared.global [%0], [%1], 16, %2;" :: "r"(s), "l"(gmem), "r"(src_sz));
}
__device__ __forceinline__ void cp_commit() { asm volatile("cp.async.commit_group;"); }
__device__ __forceinline__ void cp_wait0() { asm volatile("cp.async.wait_group 0;"); }

// ---------------- fp16 mma m16n8k16 ----------------
__device__ __forceinline__ void mma_f16(float* d, const uint32_t* a, const uint32_t* b) {
    asm volatile(
        "mma.sync.aligned.m16n8k16.row.col.f32.f16.f16.f32 "
        "{%0,%1,%2,%3}, {%4,%5,%6,%7}, {%8,%9}, {%0,%1,%2,%3};"
        : "+f"(d[0]), "+f"(d[1]), "+f"(d[2]), "+f"(d[3])
        : "r"(a[0]), "r"(a[1]), "r"(a[2]), "r"(a[3]), "r"(b[0]), "r"(b[1]));
}

// ---------------- fp16 tensor GEMM: C[M,N] = A[M,K] @ BT[N,K]^T (fp16 out) -----------
// BM=128, BN=64, BK=32. 8 warps 4(m)x2(n); warp tile 32x32 = 2(m16) x 4(n8).
#define BM 128
#define BN 64
#define BKH 32
#define HS 40           // smem stride in halfs (32 + 8 pad)

__global__ __launch_bounds__(256) void hgemm_kernel(
    const __half* __restrict__ A, const __half* __restrict__ BT,
    __half* __restrict__ C, int M, int N, int K)
{
    __shared__ __half Ah[2][BM][HS];
    __shared__ __half Bh[2][BN][HS];

    const int tid = threadIdx.x;
    const int lane = tid & 31;
    const int warp = tid >> 5;
    const int warp_m = warp & 3;
    const int warp_n = warp >> 2;
    const int g = lane >> 2;
    const int t = lane & 3;

    const int brow = blockIdx.y * BM;
    const int bcol = blockIdx.x * BN;

    float c[2][4][4];
    #pragma unroll
    for (int mi = 0; mi < 2; mi++)
        #pragma unroll
        for (int ni = 0; ni < 4; ni++)
            #pragma unroll
            for (int r = 0; r < 4; r++) c[mi][ni][r] = 0.f;

    const int a_r0 = tid >> 2;
    const int a_q = (tid & 3) * 8;
    const int b_r = tid >> 2;
    const int b_q = (tid & 3) * 8;

    {
        #pragma unroll
        for (int i = 0; i < 2; i++) {
            int r = a_r0 + i * 64;
            int gr = brow + r;
            int sz = (gr < M) ? 16 : 0;
            if (gr >= M) gr = 0;
            cp_async16(&Ah[0][r][a_q], &A[(long)gr * K + a_q], sz);
        }
        cp_async16(&Bh[0][b_r][b_q], &BT[(long)(bcol + b_r) * K + b_q], 16);
        cp_commit();
    }

    const int nk = K / BKH;
    int buf = 0;
    for (int tt = 0; tt < nk; tt++) {
        cp_wait0();
        __syncthreads();

        if (tt + 1 < nk) {
            int k0 = (tt + 1) * BKH;
            #pragma unroll
            for (int i = 0; i < 2; i++) {
                int r = a_r0 + i * 64;
                int gr = brow + r;
                int sz = (gr < M) ? 16 : 0;
                if (gr >= M) gr = 0;
                cp_async16(&Ah[buf ^ 1][r][a_q], &A[(long)gr * K + k0 + a_q], sz);
            }
            cp_async16(&Bh[buf ^ 1][b_r][b_q], &BT[(long)(bcol + b_r) * K + k0 + b_q], 16);
            cp_commit();
        }

        #pragma unroll
        for (int kk = 0; kk < BKH / 16; kk++) {
            const int ko = kk * 16;
            uint32_t a[2][4], b[4][2];
            #pragma unroll
            for (int mi = 0; mi < 2; mi++) {
                int row = warp_m * 32 + mi * 16 + g;
                a[mi][0] = *(const uint32_t*)&Ah[buf][row][ko + 2 * t];
                a[mi][1] = *(const uint32_t*)&Ah[buf][row + 8][ko + 2 * t];
                a[mi][2] = *(const uint32_t*)&Ah[buf][row][ko + 2 * t + 8];
                a[mi][3] = *(const uint32_t*)&Ah[buf][row + 8][ko + 2 * t + 8];
            }
            #pragma unroll
            for (int ni = 0; ni < 4; ni++) {
                int col = warp_n * 32 + ni * 8 + g;
                b[ni][0] = *(const uint32_t*)&Bh[buf][col][ko + 2 * t];
                b[ni][1] = *(const uint32_t*)&Bh[buf][col][ko + 2 * t + 8];
            }
            #pragma unroll
            for (int mi = 0; mi < 2; mi++)
                #pragma unroll
                for (int ni = 0; ni < 4; ni++)
                    mma_f16(c[mi][ni], a[mi], b[ni]);
        }
        buf ^= 1;
    }

    #pragma unroll
    for (int mi = 0; mi < 2; mi++) {
        int row0 = brow + warp_m * 32 + mi * 16 + g;
        int row1 = row0 + 8;
        #pragma unroll
        for (int ni = 0; ni < 4; ni++) {
            int col = bcol + warp_n * 32 + ni * 8 + t * 2;
            if (row0 < M) {
                __half2 v = __float22half2_rn(make_float2(c[mi][ni][0], c[mi][ni][1]));
                *(__half2*)&C[(long)row0 * N + col] = v;
            }
            if (row1 < M) {
                __half2 v = __float22half2_rn(make_float2(c[mi][ni][2], c[mi][ni][3]));
                *(__half2*)&C[(long)row1 * N + col] = v;
            }
        }
    }
}

// ---------------- fused pre-pass conversions ----------------
// covers x (NN*IND/2 half2), W1^T (F1*IND), W2^T (DOUT*F1)
__global__ void cvt_kernel(const float* __restrict__ x, const float* __restrict__ W1,
                           const float* __restrict__ W2)
{
    int t = blockIdx.x * blockDim.x + threadIdx.x;
    int nx = NN * IND / 2;
    if (t < nx) {
        float2 v = ((const float2*)x)[t];
        ((__half2*)g_xh)[t] = __float22half2_rn(v);
    }
    if (t < F1 * IND) {
        int n = t / IND, k = t % IND;
        g_w1t[t] = __float2half_rn(W1[k * F1 + n]);
    }
    if (t < DOUT * F1) {
        int n = t / F1, k = t % F1;
        g_w2t[t] = __float2half_rn(W2[k * DOUT + n]);
    }
}

// ---------------- CSR build ----------------
__global__ void hist_kernel(const int* __restrict__ dst)
{
    int e = blockIdx.x * blockDim.x + threadIdx.x;
    if (e < NE) atomicAdd(&g_cnt[dst[e]], 1);
}

__global__ __launch_bounds__(1024) void scan_kernel()
{
    __shared__ int sums[1024];
    const int t = threadIdx.x;
    const int CH = (NN + 1023) / 1024;
    int lo = t * CH, hi = min(lo + CH, NN);
    int s = 0;
    for (int i = lo; i < hi; i++) s += g_cnt[i];
    sums[t] = s;
    __syncthreads();
    for (int off = 1; off < 1024; off <<= 1) {
        int v = (t >= off) ? sums[t - off] : 0;
        __syncthreads();
        sums[t] += v;
        __syncthreads();
    }
    int run = (t == 0) ? 0 : sums[t - 1];
    for (int i = lo; i < hi; i++) {
        int c = g_cnt[i];
        g_off[i] = run;
        g_cur[i] = run;
        g_cnt[i] = 0;
        run += c;
    }
    if (t == 0) g_off[NN] = NE;
}

__global__ void build_csr_kernel(const int* __restrict__ src, const int* __restrict__ dst)
{
    int e = blockIdx.x * blockDim.x + threadIdx.x;
    if (e >= NE) return;
    int pos = atomicAdd(&g_cur[dst[e]], 1);
    g_csr_src[pos] = src[e];
}

// ---------------- layer 1: el/er per (node, head), fp16 features ----------------
__global__ void elr1_kernel(const float* __restrict__ al, const float* __restrict__ ar)
{
    int t = blockIdx.x * blockDim.x + threadIdx.x;
    if (t >= NN * HEADS) return;
    int n = t >> 2, h = t & 3;
    const __half2* f = (const __half2*)&g_feat1h[n * F1 + h * HID];
    const float2* a = (const float2*)&al[h * HID];
    const float2* b = (const float2*)&ar[h * HID];
    float el = 0.f, er = 0.f;
    #pragma unroll
    for (int i = 0; i < HID / 2; i++) {
        float2 fv = __half22float2(f[i]);
        float2 av = a[i], bv = b[i];
        el += fv.x * av.x + fv.y * av.y;
        er += fv.x * bv.x + fv.y * bv.y;
    }
    g_el1[t] = el;
    g_er1[t] = er;
}

// ---------------- layer 1: fused softmax + fp16 gather-agg + elu (unroll-4) ----------
// ONE warp per dst node. Lane owns 8 halves (16B); head h = lane>>3.
__global__ __launch_bounds__(256) void agg1_kernel()
{
    int d = (blockIdx.x * blockDim.x + threadIdx.x) >> 5;
    int lane = threadIdx.x & 31;
    if (d >= NN) return;
    const int lo = g_off[d], deg = g_off[d + 1] - lo;
    const int h = lane >> 3;
    const int fo = lane * 8;            // offset in halves within the 256-wide row

    const float er = g_er1[d * 4 + h];

    float acc0[8] = {};
    float acc1[8] = {};
    float wsum = 0.f;

    int j = 0;
    for (; j + 4 <= deg; j += 4) {
        int s0 = g_csr_src[lo + j + 0];
        int s1 = g_csr_src[lo + j + 1];
        int s2 = g_csr_src[lo + j + 2];
        int s3 = g_csr_src[lo + j + 3];
        float el0 = g_el1[s0 * 4 + h];
        float el1 = g_el1[s1 * 4 + h];
        float el2 = g_el1[s2 * 4 + h];
        float el3 = g_el1[s3 * 4 + h];
        uint4 r0 = *(const uint4*)&g_feat1h[s0 * F1 + fo];
        uint4 r1 = *(const uint4*)&g_feat1h[s1 * F1 + fo];
        uint4 r2 = *(const uint4*)&g_feat1h[s2 * F1 + fo];
        uint4 r3 = *(const uint4*)&g_feat1h[s3 * F1 + fo];
        float w0 = __expf(lrelu(el0 + er));
        float w1 = __expf(lrelu(el1 + er));
        float w2 = __expf(lrelu(el2 + er));
        float w3 = __expf(lrelu(el3 + er));
        wsum += (w0 + w1) + (w2 + w3);
        const uint32_t* p0 = &r0.x;
        const uint32_t* p1 = &r1.x;
        const uint32_t* p2 = &r2.x;
        const uint32_t* p3 = &r3.x;
        #pragma unroll
        for (int q = 0; q < 4; q++) {
            float2 f0 = __half22float2(*(const __half2*)&p0[q]);
            float2 f1 = __half22float2(*(const __half2*)&p1[q]);
            float2 f2 = __half22float2(*(const __half2*)&p2[q]);
            float2 f3 = __half22float2(*(const __half2*)&p3[q]);
            acc0[q * 2 + 0] = fmaf(w0, f0.x, acc0[q * 2 + 0]);
            acc0[q * 2 + 1] = fmaf(w0, f0.y, acc0[q * 2 + 1]);
            acc1[q * 2 + 0] = fmaf(w1, f1.x, acc1[q * 2 + 0]);
            acc1[q * 2 + 1] = fmaf(w1, f1.y, acc1[q * 2 + 1]);
            acc0[q * 2 + 0] = fmaf(w2, f2.x, acc0[q * 2 + 0]);
            acc0[q * 2 + 1] = fmaf(w2, f2.y, acc0[q * 2 + 1]);
            acc1[q * 2 + 0] = fmaf(w3, f3.x, acc1[q * 2 + 0]);
            acc1[q * 2 + 1] = fmaf(w3, f3.y, acc1[q * 2 + 1]);
        }
    }
    for (; j < deg; j++) {
        int s = g_csr_src[lo + j];
        float w = __expf(lrelu(g_el1[s * 4 + h] + er));
        wsum += w;
        uint4 r = *(const uint4*)&g_feat1h[s * F1 + fo];
        const uint32_t* p = &r.x;
        #pragma unroll
        for (int q = 0; q < 4; q++) {
            float2 f = __half22float2(*(const __half2*)&p[q]);
            acc0[q * 2 + 0] = fmaf(w, f.x, acc0[q * 2 + 0]);
            acc0[q * 2 + 1] = fmaf(w, f.y, acc0[q * 2 + 1]);
        }
    }
    float inv = (deg > 0) ? (1.f / wsum) : 0.f;
    uint4 outp;
    uint32_t* po = &outp.x;
    #pragma unroll
    for (int q = 0; q < 4; q++) {
        float v0 = (acc0[q * 2 + 0] + acc1[q * 2 + 0]) * inv;
        float v1 = (acc0[q * 2 + 1] + acc1[q * 2 + 1]) * inv;
        v0 = v0 > 0.f ? v0 : expm1f(v0);
        v1 = v1 > 0.f ? v1 : expm1f(v1);
        __half2 hv = __float22half2_rn(make_float2(v0, v1));
        po[q] = *(uint32_t*)&hv;
    }
    *(uint4*)&g_h1h[d * F1 + fo] = outp;
}

// ---------------- layer 2: el/er per node, fp16 features ----------------
__global__ void elr2_kernel(const float* __restrict__ al, const float* __restrict__ ar)
{
    int n = blockIdx.x * blockDim.x + threadIdx.x;
    if (n >= NN) return;
    const __half2* f = (const __half2*)&g_feat2h[n * DOUT];
    const float2* a = (const float2*)al;
    const float2* b = (const float2*)ar;
    float el = 0.f, er = 0.f;
    #pragma unroll
    for (int i = 0; i < DOUT / 2; i++) {
        float2 fv = __half22float2(f[i]);
        float2 av = a[i], bv = b[i];
        el += fv.x * av.x + fv.y * av.y;
        er += fv.x * bv.x + fv.y * bv.y;
    }
    g_el2[n] = el;
    g_er2[n] = er;
}

// ---------------- layer 2: fused softmax + fp16 gather-agg -> out (unroll-4) ----------
__global__ __launch_bounds__(256) void agg2_kernel(float* __restrict__ out)
{
    int d = (blockIdx.x * blockDim.x + threadIdx.x) >> 5;
    int lane = threadIdx.x & 31;
    if (d >= NN) return;
    const int lo = g_off[d], deg = g_off[d + 1] - lo;

    const float er = g_er2[d];

    float a0 = 0.f, a1 = 0.f, b0 = 0.f, b1 = 0.f, wsum = 0.f;
    int j = 0;
    for (; j + 4 <= deg; j += 4) {
        int s0 = g_csr_src[lo + j + 0];
        int s1 = g_csr_src[lo + j + 1];
        int s2 = g_csr_src[lo + j + 2];
        int s3 = g_csr_src[lo + j + 3];
        float e0 = g_el2[s0], e1 = g_el2[s1], e2 = g_el2[s2], e3 = g_el2[s3];
        float2 f0 = __half22float2(*(const __half2*)&g_feat2h[s0 * DOUT + lane * 2]);
        float2 f1 = __half22float2(*(const __half2*)&g_feat2h[s1 * DOUT + lane * 2]);
        float2 f2 = __half22float2(*(const __half2*)&g_feat2h[s2 * DOUT + lane * 2]);
        float2 f3 = __half22float2(*(const __half2*)&g_feat2h[s3 * DOUT + lane * 2]);
        float w0 = __expf(lrelu(e0 + er));
        float w1 = __expf(lrelu(e1 + er));
        float w2 = __expf(lrelu(e2 + er));
        float w3 = __expf(lrelu(e3 + er));
        wsum += (w0 + w1) + (w2 + w3);
        a0 = fmaf(w0, f0.x, a0); a1 = fmaf(w0, f0.y, a1);
        b0 = fmaf(w1, f1.x, b0); b1 = fmaf(w1, f1.y, b1);
        a0 = fmaf(w2, f2.x, a0); a1 = fmaf(w2, f2.y, a1);
        b0 = fmaf(w3, f3.x, b0); b1 = fmaf(w3, f3.y, b1);
    }
    for (; j < deg; j++) {
        int s = g_csr_src[lo + j];
        float w = __expf(lrelu(g_el2[s] + er));
        wsum += w;
        float2 f = __half22float2(*(const __half2*)&g_feat2h[s * DOUT + lane * 2]);
        a0 = fmaf(w, f.x, a0); a1 = fmaf(w, f.y, a1);
    }
    float inv = (deg > 0) ? (1.f / wsum) : 0.f;
    *(float2*)&out[d * DOUT + lane * 2] = make_float2((a0 + b0) * inv, (a1 + b1) * inv);
}

// ---------------- launch ----------------
extern "C" void kernel_launch(void* const* d_in, const int* in_sizes, int n_in,
                              void* d_out, int out_size)
{
    const float* x   = (const float*)d_in[0];
    const int*   src = (const int*)d_in[1];
    const int*   dst = (const int*)d_in[2];
    const float* W1  = (const float*)d_in[3];
    const float* al1 = (const float*)d_in[4];
    const float* ar1 = (const float*)d_in[5];
    const float* W2  = (const float*)d_in[6];
    const float* al2 = (const float*)d_in[7];
    const float* ar2 = (const float*)d_in[8];
    float* out = (float*)d_out;

    void *p_xh, *p_w1t, *p_w2t, *p_feat1h, *p_h1h, *p_feat2h;
    cudaGetSymbolAddress(&p_xh, g_xh);
    cudaGetSymbolAddress(&p_w1t, g_w1t);
    cudaGetSymbolAddress(&p_w2t, g_w2t);
    cudaGetSymbolAddress(&p_feat1h, g_feat1h);
    cudaGetSymbolAddress(&p_h1h, g_h1h);
    cudaGetSymbolAddress(&p_feat2h, g_feat2h);

    // fused pre-pass conversion (covers x, W1^T, W2^T)
    cvt_kernel<<<(NN * IND / 2 + 255) / 256, 256>>>(x, W1, W2);

    // CSR build
    hist_kernel<<<(NE + 255) / 256, 256>>>(dst);
    scan_kernel<<<1, 1024>>>();
    build_csr_kernel<<<(NE + 255) / 256, 256>>>(src, dst);

    // ---- layer 1 ----
    {
        dim3 grid(F1 / BN, (NN + BM - 1) / BM);
        hgemm_kernel<<<grid, 256>>>((const __half*)p_xh, (const __half*)p_w1t,
                                    (__half*)p_feat1h, NN, F1, IND);
    }
    elr1_kernel<<<(NN * HEADS + 255) / 256, 256>>>(al1, ar1);
    agg1_kernel<<<(NN * 32 + 255) / 256, 256>>>();

    // ---- layer 2 ----
    {
        dim3 grid(DOUT / BN, (NN + BM - 1) / BM);
        hgemm_kernel<<<grid, 256>>>((const __half*)p_h1h, (const __half*)p_w2t,
                                    (__half*)p_feat2h, NN, DOUT, F1);
    }
    elr2_kernel<<<(NN + 255) / 256, 256>>>(al2, ar2);
    agg2_kernel<<<(NN * 32 + 255) / 256, 256>>>(out);
}

// round 9
// speedup vs baseline: 1.2721x; 1.2721x over previous
#include <cuda_runtime.h>
#include <cuda_fp16.h>
#include <math.h>
#include <stdint.h>

#define NN 50000
#define NE 800000
#define IND 256
#define F1 256          // HEADS*HID
#define HEADS 4
#define HID 64
#define DOUT 64
#define NEG 0.2f

// ---------------- scratch (device globals: no allocation allowed) ----------------
__device__ __half g_xh[NN * IND];       // x in fp16 (GEMM1 A)
__device__ __half g_w1t[F1 * IND];      // W1^T fp16: [n][k]
__device__ __half g_w2t[DOUT * F1];     // W2^T fp16: [n][k]
__device__ __half g_feat1h[NN * F1];    // x @ W1 (fp16)
__device__ float  g_el1[NN * HEADS];
__device__ float  g_er1[NN * HEADS];
__device__ __half g_h1h[NN * F1];       // layer-1 output after elu (fp16, GEMM2 A)
__device__ __half g_feat2h[NN * DOUT];  // h1 @ W2 (fp16)
__device__ float  g_el2[NN];
__device__ float  g_er2[NN];
// CSR by dst
__device__ int g_cnt[NN];               // statically zero; re-zeroed by scan_kernel each run
__device__ int g_off[NN + 1];
__device__ int g_cur[NN];
__device__ int g_csr_src[NE];

__device__ __forceinline__ float lrelu(float v) { return v > 0.f ? v : NEG * v; }

// ---------------- cp.async helpers ----------------
__device__ __forceinline__ void cp_async16(void* smem_ptr, const void* gmem, int src_sz) {
    uint32_t s = (uint32_t)__cvta_generic_to_shared(smem_ptr);
    asm volatile("cp.async.cg.shared.global [%0], [%1], 16, %2;" :: "r"(s), "l"(gmem), "r"(src_sz));
}
__device__ __forceinline__ void cp_commit() { asm volatile("cp.async.commit_group;"); }
__device__ __forceinline__ void cp_wait0() { asm volatile("cp.async.wait_group 0;"); }

// ---------------- fp16 mma m16n8k16 ----------------
__device__ __forceinline__ void mma_f16(float* d, const uint32_t* a, const uint32_t* b) {
    asm volatile(
        "mma.sync.aligned.m16n8k16.row.col.f32.f16.f16.f32 "
        "{%0,%1,%2,%3}, {%4,%5,%6,%7}, {%8,%9}, {%0,%1,%2,%3};"
        : "+f"(d[0]), "+f"(d[1]), "+f"(d[2]), "+f"(d[3])
        : "r"(a[0]), "r"(a[1]), "r"(a[2]), "r"(a[3]), "r"(b[0]), "r"(b[1]));
}

// ---------------- fp16 tensor GEMM: C[M,N] = A[M,K] @ BT[N,K]^T (fp16 out) -----------
#define BM 128
#define BN 64
#define BKH 32
#define HS 40           // smem stride in halfs (32 + 8 pad)

__global__ __launch_bounds__(256) void hgemm_kernel(
    const __half* __restrict__ A, const __half* __restrict__ BT,
    __half* __restrict__ C, int M, int N, int K)
{
    __shared__ __half Ah[2][BM][HS];
    __shared__ __half Bh[2][BN][HS];

    const int tid = threadIdx.x;
    const int lane = tid & 31;
    const int warp = tid >> 5;
    const int warp_m = warp & 3;
    const int warp_n = warp >> 2;
    const int g = lane >> 2;
    const int t = lane & 3;

    const int brow = blockIdx.y * BM;
    const int bcol = blockIdx.x * BN;

    float c[2][4][4];
    #pragma unroll
    for (int mi = 0; mi < 2; mi++)
        #pragma unroll
        for (int ni = 0; ni < 4; ni++)
            #pragma unroll
            for (int r = 0; r < 4; r++) c[mi][ni][r] = 0.f;

    const int a_r0 = tid >> 2;
    const int a_q = (tid & 3) * 8;
    const int b_r = tid >> 2;
    const int b_q = (tid & 3) * 8;

    {
        #pragma unroll
        for (int i = 0; i < 2; i++) {
            int r = a_r0 + i * 64;
            int gr = brow + r;
            int sz = (gr < M) ? 16 : 0;
            if (gr >= M) gr = 0;
            cp_async16(&Ah[0][r][a_q], &A[(long)gr * K + a_q], sz);
        }
        cp_async16(&Bh[0][b_r][b_q], &BT[(long)(bcol + b_r) * K + b_q], 16);
        cp_commit();
    }

    const int nk = K / BKH;
    int buf = 0;
    for (int tt = 0; tt < nk; tt++) {
        cp_wait0();
        __syncthreads();

        if (tt + 1 < nk) {
            int k0 = (tt + 1) * BKH;
            #pragma unroll
            for (int i = 0; i < 2; i++) {
                int r = a_r0 + i * 64;
                int gr = brow + r;
                int sz = (gr < M) ? 16 : 0;
                if (gr >= M) gr = 0;
                cp_async16(&Ah[buf ^ 1][r][a_q], &A[(long)gr * K + k0 + a_q], sz);
            }
            cp_async16(&Bh[buf ^ 1][b_r][b_q], &BT[(long)(bcol + b_r) * K + k0 + b_q], 16);
            cp_commit();
        }

        #pragma unroll
        for (int kk = 0; kk < BKH / 16; kk++) {
            const int ko = kk * 16;
            uint32_t a[2][4], b[4][2];
            #pragma unroll
            for (int mi = 0; mi < 2; mi++) {
                int row = warp_m * 32 + mi * 16 + g;
                a[mi][0] = *(const uint32_t*)&Ah[buf][row][ko + 2 * t];
                a[mi][1] = *(const uint32_t*)&Ah[buf][row + 8][ko + 2 * t];
                a[mi][2] = *(const uint32_t*)&Ah[buf][row][ko + 2 * t + 8];
                a[mi][3] = *(const uint32_t*)&Ah[buf][row + 8][ko + 2 * t + 8];
            }
            #pragma unroll
            for (int ni = 0; ni < 4; ni++) {
                int col = warp_n * 32 + ni * 8 + g;
                b[ni][0] = *(const uint32_t*)&Bh[buf][col][ko + 2 * t];
                b[ni][1] = *(const uint32_t*)&Bh[buf][col][ko + 2 * t + 8];
            }
            #pragma unroll
            for (int mi = 0; mi < 2; mi++)
                #pragma unroll
                for (int ni = 0; ni < 4; ni++)
                    mma_f16(c[mi][ni], a[mi], b[ni]);
        }
        buf ^= 1;
    }

    #pragma unroll
    for (int mi = 0; mi < 2; mi++) {
        int row0 = brow + warp_m * 32 + mi * 16 + g;
        int row1 = row0 + 8;
        #pragma unroll
        for (int ni = 0; ni < 4; ni++) {
            int col = bcol + warp_n * 32 + ni * 8 + t * 2;
            if (row0 < M) {
                __half2 v = __float22half2_rn(make_float2(c[mi][ni][0], c[mi][ni][1]));
                *(__half2*)&C[(long)row0 * N + col] = v;
            }
            if (row1 < M) {
                __half2 v = __float22half2_rn(make_float2(c[mi][ni][2], c[mi][ni][3]));
                *(__half2*)&C[(long)row1 * N + col] = v;
            }
        }
    }
}

// ---------------- fused pre-pass conversions ----------------
__global__ void cvt_kernel(const float* __restrict__ x, const float* __restrict__ W1,
                           const float* __restrict__ W2)
{
    int t = blockIdx.x * blockDim.x + threadIdx.x;
    int nx = NN * IND / 2;
    if (t < nx) {
        float2 v = ((const float2*)x)[t];
        ((__half2*)g_xh)[t] = __float22half2_rn(v);
    }
    if (t < F1 * IND) {
        int n = t / IND, k = t % IND;
        g_w1t[t] = __float2half_rn(W1[k * F1 + n]);
    }
    if (t < DOUT * F1) {
        int n = t / F1, k = t % F1;
        g_w2t[t] = __float2half_rn(W2[k * DOUT + n]);
    }
}

// ---------------- CSR build ----------------
__global__ void hist_kernel(const int* __restrict__ dst)
{
    int e = blockIdx.x * blockDim.x + threadIdx.x;
    if (e < NE) atomicAdd(&g_cnt[dst[e]], 1);
}

__global__ __launch_bounds__(1024) void scan_kernel()
{
    __shared__ int sums[1024];
    const int t = threadIdx.x;
    const int CH = (NN + 1023) / 1024;
    int lo = t * CH, hi = min(lo + CH, NN);
    int s = 0;
    for (int i = lo; i < hi; i++) s += g_cnt[i];
    sums[t] = s;
    __syncthreads();
    for (int off = 1; off < 1024; off <<= 1) {
        int v = (t >= off) ? sums[t - off] : 0;
        __syncthreads();
        sums[t] += v;
        __syncthreads();
    }
    int run = (t == 0) ? 0 : sums[t - 1];
    for (int i = lo; i < hi; i++) {
        int c = g_cnt[i];
        g_off[i] = run;
        g_cur[i] = run;
        g_cnt[i] = 0;
        run += c;
    }
    if (t == 0) g_off[NN] = NE;
}

__global__ void build_csr_kernel(const int* __restrict__ src, const int* __restrict__ dst)
{
    int e = blockIdx.x * blockDim.x + threadIdx.x;
    if (e >= NE) return;
    int pos = atomicAdd(&g_cur[dst[e]], 1);
    g_csr_src[pos] = src[e];
}

// ---------------- layer 1: el/er per (node, head), fp16 features ----------------
__global__ void elr1_kernel(const float* __restrict__ al, const float* __restrict__ ar)
{
    int t = blockIdx.x * blockDim.x + threadIdx.x;
    if (t >= NN * HEADS) return;
    int n = t >> 2, h = t & 3;
    const __half2* f = (const __half2*)&g_feat1h[n * F1 + h * HID];
    const float2* a = (const float2*)&al[h * HID];
    const float2* b = (const float2*)&ar[h * HID];
    float el = 0.f, er = 0.f;
    #pragma unroll
    for (int i = 0; i < HID / 2; i++) {
        float2 fv = __half22float2(f[i]);
        float2 av = a[i], bv = b[i];
        el += fv.x * av.x + fv.y * av.y;
        er += fv.x * bv.x + fv.y * bv.y;
    }
    g_el1[t] = el;
    g_er1[t] = er;
}

// ---------------- layer 1: fused softmax + fp16 gather-agg + elu (unroll-4) ----------
__global__ __launch_bounds__(256) void agg1_kernel()
{
    int d = (blockIdx.x * blockDim.x + threadIdx.x) >> 5;
    int lane = threadIdx.x & 31;
    if (d >= NN) return;
    const int lo = g_off[d], deg = g_off[d + 1] - lo;
    const int h = lane >> 3;
    const int fo = lane * 8;

    const float er = g_er1[d * 4 + h];

    float acc0[8] = {};
    float acc1[8] = {};
    float wsum = 0.f;

    int j = 0;
    for (; j + 4 <= deg; j += 4) {
        int s0 = g_csr_src[lo + j + 0];
        int s1 = g_csr_src[lo + j + 1];
        int s2 = g_csr_src[lo + j + 2];
        int s3 = g_csr_src[lo + j + 3];
        float el0 = g_el1[s0 * 4 + h];
        float el1 = g_el1[s1 * 4 + h];
        float el2 = g_el1[s2 * 4 + h];
        float el3 = g_el1[s3 * 4 + h];
        uint4 r0 = *(const uint4*)&g_feat1h[s0 * F1 + fo];
        uint4 r1 = *(const uint4*)&g_feat1h[s1 * F1 + fo];
        uint4 r2 = *(const uint4*)&g_feat1h[s2 * F1 + fo];
        uint4 r3 = *(const uint4*)&g_feat1h[s3 * F1 + fo];
        float w0 = __expf(lrelu(el0 + er));
        float w1 = __expf(lrelu(el1 + er));
        float w2 = __expf(lrelu(el2 + er));
        float w3 = __expf(lrelu(el3 + er));
        wsum += (w0 + w1) + (w2 + w3);
        const uint32_t* p0 = &r0.x;
        const uint32_t* p1 = &r1.x;
        const uint32_t* p2 = &r2.x;
        const uint32_t* p3 = &r3.x;
        #pragma unroll
        for (int q = 0; q < 4; q++) {
            float2 f0 = __half22float2(*(const __half2*)&p0[q]);
            float2 f1 = __half22float2(*(const __half2*)&p1[q]);
            float2 f2 = __half22float2(*(const __half2*)&p2[q]);
            float2 f3 = __half22float2(*(const __half2*)&p3[q]);
            acc0[q * 2 + 0] = fmaf(w0, f0.x, acc0[q * 2 + 0]);
            acc0[q * 2 + 1] = fmaf(w0, f0.y, acc0[q * 2 + 1]);
            acc1[q * 2 + 0] = fmaf(w1, f1.x, acc1[q * 2 + 0]);
            acc1[q * 2 + 1] = fmaf(w1, f1.y, acc1[q * 2 + 1]);
            acc0[q * 2 + 0] = fmaf(w2, f2.x, acc0[q * 2 + 0]);
            acc0[q * 2 + 1] = fmaf(w2, f2.y, acc0[q * 2 + 1]);
            acc1[q * 2 + 0] = fmaf(w3, f3.x, acc1[q * 2 + 0]);
            acc1[q * 2 + 1] = fmaf(w3, f3.y, acc1[q * 2 + 1]);
        }
    }
    for (; j < deg; j++) {
        int s = g_csr_src[lo + j];
        float w = __expf(lrelu(g_el1[s * 4 + h] + er));
        wsum += w;
        uint4 r = *(const uint4*)&g_feat1h[s * F1 + fo];
        const uint32_t* p = &r.x;
        #pragma unroll
        for (int q = 0; q < 4; q++) {
            float2 f = __half22float2(*(const __half2*)&p[q]);
            acc0[q * 2 + 0] = fmaf(w, f.x, acc0[q * 2 + 0]);
            acc0[q * 2 + 1] = fmaf(w, f.y, acc0[q * 2 + 1]);
        }
    }
    float inv = (deg > 0) ? (1.f / wsum) : 0.f;
    uint4 outp;
    uint32_t* po = &outp.x;
    #pragma unroll
    for (int q = 0; q < 4; q++) {
        float v0 = (acc0[q * 2 + 0] + acc1[q * 2 + 0]) * inv;
        float v1 = (acc0[q * 2 + 1] + acc1[q * 2 + 1]) * inv;
        v0 = v0 > 0.f ? v0 : expm1f(v0);
        v1 = v1 > 0.f ? v1 : expm1f(v1);
        __half2 hv = __float22half2_rn(make_float2(v0, v1));
        po[q] = *(uint32_t*)&hv;
    }
    *(uint4*)&g_h1h[d * F1 + fo] = outp;
}

// ---------------- layer 2: el/er per node, fp16 features ----------------
__global__ void elr2_kernel(const float* __restrict__ al, const float* __restrict__ ar)
{
    int n = blockIdx.x * blockDim.x + threadIdx.x;
    if (n >= NN) return;
    const __half2* f = (const __half2*)&g_feat2h[n * DOUT];
    const float2* a = (const float2*)al;
    const float2* b = (const float2*)ar;
    float el = 0.f, er = 0.f;
    #pragma unroll
    for (int i = 0; i < DOUT / 2; i++) {
        float2 fv = __half22float2(f[i]);
        float2 av = a[i], bv = b[i];
        el += fv.x * av.x + fv.y * av.y;
        er += fv.x * bv.x + fv.y * bv.y;
    }
    g_el2[n] = el;
    g_er2[n] = er;
}

// ---------------- layer 2: fused softmax + fp16 gather-agg -> out (unroll-8) ----------
__global__ __launch_bounds__(256) void agg2_kernel(float* __restrict__ out)
{
    int d = (blockIdx.x * blockDim.x + threadIdx.x) >> 5;
    int lane = threadIdx.x & 31;
    if (d >= NN) return;
    const int lo = g_off[d], deg = g_off[d + 1] - lo;

    const float er = g_er2[d];

    float a0 = 0.f, a1 = 0.f, b0 = 0.f, b1 = 0.f, wsum = 0.f;
    int j = 0;
    for (; j + 8 <= deg; j += 8) {
        int s[8];
        #pragma unroll
        for (int q = 0; q < 8; q++) s[q] = g_csr_src[lo + j + q];
        float e[8];
        #pragma unroll
        for (int q = 0; q < 8; q++) e[q] = g_el2[s[q]];
        float2 f[8];
        #pragma unroll
        for (int q = 0; q < 8; q++)
            f[q] = __half22float2(*(const __half2*)&g_feat2h[s[q] * DOUT + lane * 2]);
        float w[8];
        #pragma unroll
        for (int q = 0; q < 8; q++) w[q] = __expf(lrelu(e[q] + er));
        #pragma unroll
        for (int q = 0; q < 8; q++) wsum += w[q];
        #pragma unroll
        for (int q = 0; q < 8; q += 2) {
            a0 = fmaf(w[q], f[q].x, a0);     a1 = fmaf(w[q], f[q].y, a1);
            b0 = fmaf(w[q + 1], f[q + 1].x, b0); b1 = fmaf(w[q + 1], f[q + 1].y, b1);
        }
    }
    for (; j < deg; j++) {
        int s = g_csr_src[lo + j];
        float w = __expf(lrelu(g_el2[s] + er));
        wsum += w;
        float2 f = __half22float2(*(const __half2*)&g_feat2h[s * DOUT + lane * 2]);
        a0 = fmaf(w, f.x, a0); a1 = fmaf(w, f.y, a1);
    }
    float inv = (deg > 0) ? (1.f / wsum) : 0.f;
    *(float2*)&out[d * DOUT + lane * 2] = make_float2((a0 + b0) * inv, (a1 + b1) * inv);
}

// ---------------- launch ----------------
extern "C" void kernel_launch(void* const* d_in, const int* in_sizes, int n_in,
                              void* d_out, int out_size)
{
    const float* x   = (const float*)d_in[0];
    const int*   src = (const int*)d_in[1];
    const int*   dst = (const int*)d_in[2];
    const float* W1  = (const float*)d_in[3];
    const float* al1 = (const float*)d_in[4];
    const float* ar1 = (const float*)d_in[5];
    const float* W2  = (const float*)d_in[6];
    const float* al2 = (const float*)d_in[7];
    const float* ar2 = (const float*)d_in[8];
    float* out = (float*)d_out;

    void *p_xh, *p_w1t, *p_w2t, *p_feat1h, *p_h1h, *p_feat2h;
    cudaGetSymbolAddress(&p_xh, g_xh);
    cudaGetSymbolAddress(&p_w1t, g_w1t);
    cudaGetSymbolAddress(&p_w2t, g_w2t);
    cudaGetSymbolAddress(&p_feat1h, g_feat1h);
    cudaGetSymbolAddress(&p_h1h, g_h1h);
    cudaGetSymbolAddress(&p_feat2h, g_feat2h);

    // Side stream + events for a parallel CSR branch in the captured graph.
    // Host-side objects only (no device memory); created once and cached.
    static cudaStream_t sA = nullptr;
    static cudaEvent_t evFork = nullptr, evJoin = nullptr;
    if (sA == nullptr) {
        cudaStreamCreateWithFlags(&sA, cudaStreamNonBlocking);
        cudaEventCreateWithFlags(&evFork, cudaEventDisableTiming);
        cudaEventCreateWithFlags(&evJoin, cudaEventDisableTiming);
    }

    // ---- fork: CSR build chain on side stream ----
    cudaEventRecord(evFork, 0);
    cudaStreamWaitEvent(sA, evFork, 0);
    hist_kernel<<<(NE + 255) / 256, 256, 0, sA>>>(dst);
    scan_kernel<<<1, 1024, 0, sA>>>();
    build_csr_kernel<<<(NE + 255) / 256, 256, 0, sA>>>(src, dst);
    cudaEventRecord(evJoin, sA);

    // ---- main stream: conversions + layer-1 GEMM + el/er ----
    cvt_kernel<<<(NN * IND / 2 + 255) / 256, 256>>>(x, W1, W2);
    {
        dim3 grid(F1 / BN, (NN + BM - 1) / BM);
        hgemm_kernel<<<grid, 256>>>((const __half*)p_xh, (const __half*)p_w1t,
                                    (__half*)p_feat1h, NN, F1, IND);
    }
    elr1_kernel<<<(NN * HEADS + 255) / 256, 256>>>(al1, ar1);

    // ---- join: CSR must be ready before aggregation ----
    cudaStreamWaitEvent(0, evJoin, 0);

    agg1_kernel<<<(NN * 32 + 255) / 256, 256>>>();

    // ---- layer 2 ----
    {
        dim3 grid(DOUT / BN, (NN + BM - 1) / BM);
        hgemm_kernel<<<grid, 256>>>((const __half*)p_h1h, (const __half*)p_w2t,
                                    (__half*)p_feat2h, NN, DOUT, F1);
    }
    elr2_kernel<<<(NN + 255) / 256, 256>>>(al2, ar2);
    agg2_kernel<<<(NN * 32 + 255) / 256, 256>>>(out);
}

// round 10
// speedup vs baseline: 1.2797x; 1.0060x over previous
#include <cuda_runtime.h>
#include <cuda_fp16.h>
#include <math.h>
#include <stdint.h>

#define NN 50000
#define NE 800000
#define IND 256
#define F1 256          // HEADS*HID
#define HEADS 4
#define HID 64
#define DOUT 64
#define NEG 0.2f

// ---------------- scratch (device globals: no allocation allowed) ----------------
__device__ __half g_xh[NN * IND];       // x in fp16 (GEMM1 A)
__device__ __half g_w1t[F1 * IND];      // W1^T fp16: [n][k]
__device__ __half g_w2t[DOUT * F1];     // W2^T fp16: [n][k]
__device__ __half g_feat1h[NN * F1];    // x @ W1 (fp16)
__device__ float  g_el1[NN * HEADS];
__device__ float  g_er1[NN * HEADS];
__device__ __half g_h1h[NN * F1];       // layer-1 output after elu (fp16, GEMM2 A)
__device__ __half g_feat2h[NN * DOUT];  // h1 @ W2 (fp16)
__device__ float  g_el2[NN];
__device__ float  g_er2[NN];
// CSR by dst
__device__ int g_cnt[NN];               // statically zero; re-zeroed by scan_kernel each run
__device__ int g_off[NN + 1];
__device__ int g_cur[NN];
__device__ int g_csr_src[NE];

__device__ __forceinline__ float lrelu(float v) { return v > 0.f ? v : NEG * v; }

// ---------------- cp.async helpers ----------------
__device__ __forceinline__ void cp_async16(void* smem_ptr, const void* gmem, int src_sz) {
    uint32_t s = (uint32_t)__cvta_generic_to_shared(smem_ptr);
    asm volatile("cp.async.cg.shared.global [%0], [%1], 16, %2;" :: "r"(s), "l"(gmem), "r"(src_sz));
}
__device__ __forceinline__ void cp_commit() { asm volatile("cp.async.commit_group;"); }
__device__ __forceinline__ void cp_wait0() { asm volatile("cp.async.wait_group 0;"); }

// ---------------- fp16 mma m16n8k16 ----------------
__device__ __forceinline__ void mma_f16(float* d, const uint32_t* a, const uint32_t* b) {
    asm volatile(
        "mma.sync.aligned.m16n8k16.row.col.f32.f16.f16.f32 "
        "{%0,%1,%2,%3}, {%4,%5,%6,%7}, {%8,%9}, {%0,%1,%2,%3};"
        : "+f"(d[0]), "+f"(d[1]), "+f"(d[2]), "+f"(d[3])
        : "r"(a[0]), "r"(a[1]), "r"(a[2]), "r"(a[3]), "r"(b[0]), "r"(b[1]));
}

// ---------------- fp16 tensor GEMM: C[M,N] = A[M,K] @ BT[N,K]^T (fp16 out) -----------
#define BM 128
#define BN 64
#define BKH 32
#define HS 40           // smem stride in halfs (32 + 8 pad)

__global__ __launch_bounds__(256) void hgemm_kernel(
    const __half* __restrict__ A, const __half* __restrict__ BT,
    __half* __restrict__ C, int M, int N, int K)
{
    __shared__ __half Ah[2][BM][HS];
    __shared__ __half Bh[2][BN][HS];

    const int tid = threadIdx.x;
    const int lane = tid & 31;
    const int warp = tid >> 5;
    const int warp_m = warp & 3;
    const int warp_n = warp >> 2;
    const int g = lane >> 2;
    const int t = lane & 3;

    const int brow = blockIdx.y * BM;
    const int bcol = blockIdx.x * BN;

    float c[2][4][4];
    #pragma unroll
    for (int mi = 0; mi < 2; mi++)
        #pragma unroll
        for (int ni = 0; ni < 4; ni++)
            #pragma unroll
            for (int r = 0; r < 4; r++) c[mi][ni][r] = 0.f;

    const int a_r0 = tid >> 2;
    const int a_q = (tid & 3) * 8;
    const int b_r = tid >> 2;
    const int b_q = (tid & 3) * 8;

    {
        #pragma unroll
        for (int i = 0; i < 2; i++) {
            int r = a_r0 + i * 64;
            int gr = brow + r;
            int sz = (gr < M) ? 16 : 0;
            if (gr >= M) gr = 0;
            cp_async16(&Ah[0][r][a_q], &A[(long)gr * K + a_q], sz);
        }
        cp_async16(&Bh[0][b_r][b_q], &BT[(long)(bcol + b_r) * K + b_q], 16);
        cp_commit();
    }

    const int nk = K / BKH;
    int buf = 0;
    for (int tt = 0; tt < nk; tt++) {
        cp_wait0();
        __syncthreads();

        if (tt + 1 < nk) {
            int k0 = (tt + 1) * BKH;
            #pragma unroll
            for (int i = 0; i < 2; i++) {
                int r = a_r0 + i * 64;
                int gr = brow + r;
                int sz = (gr < M) ? 16 : 0;
                if (gr >= M) gr = 0;
                cp_async16(&Ah[buf ^ 1][r][a_q], &A[(long)gr * K + k0 + a_q], sz);
            }
            cp_async16(&Bh[buf ^ 1][b_r][b_q], &BT[(long)(bcol + b_r) * K + k0 + b_q], 16);
            cp_commit();
        }

        #pragma unroll
        for (int kk = 0; kk < BKH / 16; kk++) {
            const int ko = kk * 16;
            uint32_t a[2][4], b[4][2];
            #pragma unroll
            for (int mi = 0; mi < 2; mi++) {
                int row = warp_m * 32 + mi * 16 + g;
                a[mi][0] = *(const uint32_t*)&Ah[buf][row][ko + 2 * t];
                a[mi][1] = *(const uint32_t*)&Ah[buf][row + 8][ko + 2 * t];
                a[mi][2] = *(const uint32_t*)&Ah[buf][row][ko + 2 * t + 8];
                a[mi][3] = *(const uint32_t*)&Ah[buf][row + 8][ko + 2 * t + 8];
            }
            #pragma unroll
            for (int ni = 0; ni < 4; ni++) {
                int col = warp_n * 32 + ni * 8 + g;
                b[ni][0] = *(const uint32_t*)&Bh[buf][col][ko + 2 * t];
                b[ni][1] = *(const uint32_t*)&Bh[buf][col][ko + 2 * t + 8];
            }
            #pragma unroll
            for (int mi = 0; mi < 2; mi++)
                #pragma unroll
                for (int ni = 0; ni < 4; ni++)
                    mma_f16(c[mi][ni], a[mi], b[ni]);
        }
        buf ^= 1;
    }

    #pragma unroll
    for (int mi = 0; mi < 2; mi++) {
        int row0 = brow + warp_m * 32 + mi * 16 + g;
        int row1 = row0 + 8;
        #pragma unroll
        for (int ni = 0; ni < 4; ni++) {
            int col = bcol + warp_n * 32 + ni * 8 + t * 2;
            if (row0 < M) {
                __half2 v = __float22half2_rn(make_float2(c[mi][ni][0], c[mi][ni][1]));
                *(__half2*)&C[(long)row0 * N + col] = v;
            }
            if (row1 < M) {
                __half2 v = __float22half2_rn(make_float2(c[mi][ni][2], c[mi][ni][3]));
                *(__half2*)&C[(long)row1 * N + col] = v;
            }
        }
    }
}

// ---------------- fused pre-pass conversions ----------------
__global__ void cvt_kernel(const float* __restrict__ x, const float* __restrict__ W1,
                           const float* __restrict__ W2)
{
    int t = blockIdx.x * blockDim.x + threadIdx.x;
    int nx = NN * IND / 2;
    if (t < nx) {
        float2 v = ((const float2*)x)[t];
        ((__half2*)g_xh)[t] = __float22half2_rn(v);
    }
    if (t < F1 * IND) {
        int n = t / IND, k = t % IND;
        g_w1t[t] = __float2half_rn(W1[k * F1 + n]);
    }
    if (t < DOUT * F1) {
        int n = t / F1, k = t % F1;
        g_w2t[t] = __float2half_rn(W2[k * DOUT + n]);
    }
}

// ---------------- CSR build ----------------
__global__ void hist_kernel(const int* __restrict__ dst)
{
    int e = blockIdx.x * blockDim.x + threadIdx.x;
    if (e < NE) atomicAdd(&g_cnt[dst[e]], 1);
}

__global__ __launch_bounds__(1024) void scan_kernel()
{
    __shared__ int sums[1024];
    const int t = threadIdx.x;
    const int CH = (NN + 1023) / 1024;
    int lo = t * CH, hi = min(lo + CH, NN);
    int s = 0;
    for (int i = lo; i < hi; i++) s += g_cnt[i];
    sums[t] = s;
    __syncthreads();
    for (int off = 1; off < 1024; off <<= 1) {
        int v = (t >= off) ? sums[t - off] : 0;
        __syncthreads();
        sums[t] += v;
        __syncthreads();
    }
    int run = (t == 0) ? 0 : sums[t - 1];
    for (int i = lo; i < hi; i++) {
        int c = g_cnt[i];
        g_off[i] = run;
        g_cur[i] = run;
        g_cnt[i] = 0;
        run += c;
    }
    if (t == 0) g_off[NN] = NE;
}

__global__ void build_csr_kernel(const int* __restrict__ src, const int* __restrict__ dst)
{
    int e = blockIdx.x * blockDim.x + threadIdx.x;
    if (e >= NE) return;
    int pos = atomicAdd(&g_cur[dst[e]], 1);
    g_csr_src[pos] = src[e];
}

// ---------------- layer 1: el/er per (node, head), fp16 features ----------------
__global__ void elr1_kernel(const float* __restrict__ al, const float* __restrict__ ar)
{
    int t = blockIdx.x * blockDim.x + threadIdx.x;
    if (t >= NN * HEADS) return;
    int n = t >> 2, h = t & 3;
    const __half2* f = (const __half2*)&g_feat1h[n * F1 + h * HID];
    const float2* a = (const float2*)&al[h * HID];
    const float2* b = (const float2*)&ar[h * HID];
    float el = 0.f, er = 0.f;
    #pragma unroll
    for (int i = 0; i < HID / 2; i++) {
        float2 fv = __half22float2(f[i]);
        float2 av = a[i], bv = b[i];
        el += fv.x * av.x + fv.y * av.y;
        er += fv.x * bv.x + fv.y * bv.y;
    }
    g_el1[t] = el;
    g_er1[t] = er;
}

// ---------------- layer 1: fused softmax + fp16 gather-agg + elu (unroll-4) ----------
__global__ __launch_bounds__(256) void agg1_kernel()
{
    int d = (blockIdx.x * blockDim.x + threadIdx.x) >> 5;
    int lane = threadIdx.x & 31;
    if (d >= NN) return;
    const int lo = g_off[d], deg = g_off[d + 1] - lo;
    const int h = lane >> 3;
    const int fo = lane * 8;

    const float er = g_er1[d * 4 + h];

    float acc0[8] = {};
    float acc1[8] = {};
    float wsum = 0.f;

    int j = 0;
    for (; j + 4 <= deg; j += 4) {
        int s0 = g_csr_src[lo + j + 0];
        int s1 = g_csr_src[lo + j + 1];
        int s2 = g_csr_src[lo + j + 2];
        int s3 = g_csr_src[lo + j + 3];
        float el0 = g_el1[s0 * 4 + h];
        float el1 = g_el1[s1 * 4 + h];
        float el2 = g_el1[s2 * 4 + h];
        float el3 = g_el1[s3 * 4 + h];
        uint4 r0 = *(const uint4*)&g_feat1h[s0 * F1 + fo];
        uint4 r1 = *(const uint4*)&g_feat1h[s1 * F1 + fo];
        uint4 r2 = *(const uint4*)&g_feat1h[s2 * F1 + fo];
        uint4 r3 = *(const uint4*)&g_feat1h[s3 * F1 + fo];
        float w0 = __expf(lrelu(el0 + er));
        float w1 = __expf(lrelu(el1 + er));
        float w2 = __expf(lrelu(el2 + er));
        float w3 = __expf(lrelu(el3 + er));
        wsum += (w0 + w1) + (w2 + w3);
        const uint32_t* p0 = &r0.x;
        const uint32_t* p1 = &r1.x;
        const uint32_t* p2 = &r2.x;
        const uint32_t* p3 = &r3.x;
        #pragma unroll
        for (int q = 0; q < 4; q++) {
            float2 f0 = __half22float2(*(const __half2*)&p0[q]);
            float2 f1 = __half22float2(*(const __half2*)&p1[q]);
            float2 f2 = __half22float2(*(const __half2*)&p2[q]);
            float2 f3 = __half22float2(*(const __half2*)&p3[q]);
            acc0[q * 2 + 0] = fmaf(w0, f0.x, acc0[q * 2 + 0]);
            acc0[q * 2 + 1] = fmaf(w0, f0.y, acc0[q * 2 + 1]);
            acc1[q * 2 + 0] = fmaf(w1, f1.x, acc1[q * 2 + 0]);
            acc1[q * 2 + 1] = fmaf(w1, f1.y, acc1[q * 2 + 1]);
            acc0[q * 2 + 0] = fmaf(w2, f2.x, acc0[q * 2 + 0]);
            acc0[q * 2 + 1] = fmaf(w2, f2.y, acc0[q * 2 + 1]);
            acc1[q * 2 + 0] = fmaf(w3, f3.x, acc1[q * 2 + 0]);
            acc1[q * 2 + 1] = fmaf(w3, f3.y, acc1[q * 2 + 1]);
        }
    }
    for (; j < deg; j++) {
        int s = g_csr_src[lo + j];
        float w = __expf(lrelu(g_el1[s * 4 + h] + er));
        wsum += w;
        uint4 r = *(const uint4*)&g_feat1h[s * F1 + fo];
        const uint32_t* p = &r.x;
        #pragma unroll
        for (int q = 0; q < 4; q++) {
            float2 f = __half22float2(*(const __half2*)&p[q]);
            acc0[q * 2 + 0] = fmaf(w, f.x, acc0[q * 2 + 0]);
            acc0[q * 2 + 1] = fmaf(w, f.y, acc0[q * 2 + 1]);
        }
    }
    float inv = (deg > 0) ? (1.f / wsum) : 0.f;
    uint4 outp;
    uint32_t* po = &outp.x;
    #pragma unroll
    for (int q = 0; q < 4; q++) {
        float v0 = (acc0[q * 2 + 0] + acc1[q * 2 + 0]) * inv;
        float v1 = (acc0[q * 2 + 1] + acc1[q * 2 + 1]) * inv;
        v0 = v0 > 0.f ? v0 : expm1f(v0);
        v1 = v1 > 0.f ? v1 : expm1f(v1);
        __half2 hv = __float22half2_rn(make_float2(v0, v1));
        po[q] = *(uint32_t*)&hv;
    }
    *(uint4*)&g_h1h[d * F1 + fo] = outp;
}

// ---------------- layer 2: el/er per node, fp16 features ----------------
__global__ void elr2_kernel(const float* __restrict__ al, const float* __restrict__ ar)
{
    int n = blockIdx.x * blockDim.x + threadIdx.x;
    if (n >= NN) return;
    const __half2* f = (const __half2*)&g_feat2h[n * DOUT];
    const float2* a = (const float2*)al;
    const float2* b = (const float2*)ar;
    float el = 0.f, er = 0.f;
    #pragma unroll
    for (int i = 0; i < DOUT / 2; i++) {
        float2 fv = __half22float2(f[i]);
        float2 av = a[i], bv = b[i];
        el += fv.x * av.x + fv.y * av.y;
        er += fv.x * bv.x + fv.y * bv.y;
    }
    g_el2[n] = el;
    g_er2[n] = er;
}

// ---------------- layer 2: fused softmax + fp16 gather-agg -> out (unroll-8) ----------
__global__ __launch_bounds__(256) void agg2_kernel(float* __restrict__ out)
{
    int d = (blockIdx.x * blockDim.x + threadIdx.x) >> 5;
    int lane = threadIdx.x & 31;
    if (d >= NN) return;
    const int lo = g_off[d], deg = g_off[d + 1] - lo;

    const float er = g_er2[d];

    float a0 = 0.f, a1 = 0.f, b0 = 0.f, b1 = 0.f, wsum = 0.f;
    int j = 0;
    for (; j + 8 <= deg; j += 8) {
        int s[8];
        #pragma unroll
        for (int q = 0; q < 8; q++) s[q] = g_csr_src[lo + j + q];
        float e[8];
        #pragma unroll
        for (int q = 0; q < 8; q++) e[q] = g_el2[s[q]];
        float2 f[8];
        #pragma unroll
        for (int q = 0; q < 8; q++)
            f[q] = __half22float2(*(const __half2*)&g_feat2h[s[q] * DOUT + lane * 2]);
        float w[8];
        #pragma unroll
        for (int q = 0; q < 8; q++) w[q] = __expf(lrelu(e[q] + er));
        #pragma unroll
        for (int q = 0; q < 8; q++) wsum += w[q];
        #pragma unroll
        for (int q = 0; q < 8; q += 2) {
            a0 = fmaf(w[q], f[q].x, a0);     a1 = fmaf(w[q], f[q].y, a1);
            b0 = fmaf(w[q + 1], f[q + 1].x, b0); b1 = fmaf(w[q + 1], f[q + 1].y, b1);
        }
    }
    for (; j < deg; j++) {
        int s = g_csr_src[lo + j];
        float w = __expf(lrelu(g_el2[s] + er));
        wsum += w;
        float2 f = __half22float2(*(const __half2*)&g_feat2h[s * DOUT + lane * 2]);
        a0 = fmaf(w, f.x, a0); a1 = fmaf(w, f.y, a1);
    }
    float inv = (deg > 0) ? (1.f / wsum) : 0.f;
    *(float2*)&out[d * DOUT + lane * 2] = make_float2((a0 + b0) * inv, (a1 + b1) * inv);
}

// ---------------- launch ----------------
extern "C" void kernel_launch(void* const* d_in, const int* in_sizes, int n_in,
                              void* d_out, int out_size)
{
    const float* x   = (const float*)d_in[0];
    const int*   src = (const int*)d_in[1];
    const int*   dst = (const int*)d_in[2];
    const float* W1  = (const float*)d_in[3];
    const float* al1 = (const float*)d_in[4];
    const float* ar1 = (const float*)d_in[5];
    const float* W2  = (const float*)d_in[6];
    const float* al2 = (const float*)d_in[7];
    const float* ar2 = (const float*)d_in[8];
    float* out = (float*)d_out;

    void *p_xh, *p_w1t, *p_w2t, *p_feat1h, *p_h1h, *p_feat2h;
    cudaGetSymbolAddress(&p_xh, g_xh);
    cudaGetSymbolAddress(&p_w1t, g_w1t);
    cudaGetSymbolAddress(&p_w2t, g_w2t);
    cudaGetSymbolAddress(&p_feat1h, g_feat1h);
    cudaGetSymbolAddress(&p_h1h, g_h1h);
    cudaGetSymbolAddress(&p_feat2h, g_feat2h);

    // Side stream + events for a parallel CSR branch in the captured graph.
    // Host-side objects only (no device memory); created once and cached.
    static cudaStream_t sA = nullptr;
    static cudaEvent_t evFork = nullptr, evJoin = nullptr;
    if (sA == nullptr) {
        cudaStreamCreateWithFlags(&sA, cudaStreamNonBlocking);
        cudaEventCreateWithFlags(&evFork, cudaEventDisableTiming);
        cudaEventCreateWithFlags(&evJoin, cudaEventDisableTiming);
    }

    // ---- fork: CSR build chain on side stream ----
    cudaEventRecord(evFork, 0);
    cudaStreamWaitEvent(sA, evFork, 0);
    hist_kernel<<<(NE + 255) / 256, 256, 0, sA>>>(dst);
    scan_kernel<<<1, 1024, 0, sA>>>();
    build_csr_kernel<<<(NE + 255) / 256, 256, 0, sA>>>(src, dst);
    cudaEventRecord(evJoin, sA);

    // ---- main stream: conversions + layer-1 GEMM + el/er ----
    cvt_kernel<<<(NN * IND / 2 + 255) / 256, 256>>>(x, W1, W2);
    {
        dim3 grid(F1 / BN, (NN + BM - 1) / BM);
        hgemm_kernel<<<grid, 256>>>((const __half*)p_xh, (const __half*)p_w1t,
                                    (__half*)p_feat1h, NN, F1, IND);
    }
    elr1_kernel<<<(NN * HEADS + 255) / 256, 256>>>(al1, ar1);

    // ---- join: CSR must be ready before aggregation ----
    cudaStreamWaitEvent(0, evJoin, 0);

    agg1_kernel<<<(NN * 32 + 255) / 256, 256>>>();

    // ---- layer 2 ----
    {
        dim3 grid(DOUT / BN, (NN + BM - 1) / BM);
        hgemm_kernel<<<grid, 256>>>((const __half*)p_h1h, (const __half*)p_w2t,
                                    (__half*)p_feat2h, NN, DOUT, F1);
    }
    elr2_kernel<<<(NN + 255) / 256, 256>>>(al2, ar2);
    agg2_kernel<<<(NN * 32 + 255) / 256, 256>>>(out);
}

// round 11
// speedup vs baseline: 1.2848x; 1.0040x over previous
#include <cuda_runtime.h>
#include <cuda_fp16.h>
#include <math.h>
#include <stdint.h>

#define NN 50000
#define NE 800000
#define IND 256
#define F1 256          // HEADS*HID
#define HEADS 4
#define HID 64
#define DOUT 64
#define NEG 0.2f

// ---------------- scratch (device globals: no allocation allowed) ----------------
__device__ __half g_xh[NN * IND];       // x in fp16 (GEMM1 A)
__device__ __half g_w1t[F1 * IND];      // W1^T fp16: [n][k]
__device__ __half g_w2t[DOUT * F1];     // W2^T fp16: [n][k]
__device__ __half g_feat1h[NN * F1];    // x @ W1 (fp16)
__device__ float  g_el1[NN * HEADS];
__device__ float  g_er1[NN * HEADS];
__device__ __half g_h1h[NN * F1];       // layer-1 output after elu (fp16, GEMM2 A)
__device__ __half g_feat2h[NN * DOUT];  // h1 @ W2 (fp16)
__device__ float  g_el2[NN];
__device__ float  g_er2[NN];
// CSR by dst
__device__ int g_cnt[NN];               // statically zero; re-zeroed by scan_kernel each run
__device__ int g_off[NN + 1];
__device__ int g_cur[NN];
__device__ int g_csr_src[NE];

__device__ __forceinline__ float lrelu(float v) { return v > 0.f ? v : NEG * v; }

// ---------------- cp.async helpers ----------------
__device__ __forceinline__ void cp_async16(void* smem_ptr, const void* gmem, int src_sz) {
    uint32_t s = (uint32_t)__cvta_generic_to_shared(smem_ptr);
    asm volatile("cp.async.cg.shared.global [%0], [%1], 16, %2;" :: "r"(s), "l"(gmem), "r"(src_sz));
}
__device__ __forceinline__ void cp_commit() { asm volatile("cp.async.commit_group;"); }
__device__ __forceinline__ void cp_wait0() { asm volatile("cp.async.wait_group 0;"); }

// ---------------- fp16 mma m16n8k16 ----------------
__device__ __forceinline__ void mma_f16(float* d, const uint32_t* a, const uint32_t* b) {
    asm volatile(
        "mma.sync.aligned.m16n8k16.row.col.f32.f16.f16.f32 "
        "{%0,%1,%2,%3}, {%4,%5,%6,%7}, {%8,%9}, {%0,%1,%2,%3};"
        : "+f"(d[0]), "+f"(d[1]), "+f"(d[2]), "+f"(d[3])
        : "r"(a[0]), "r"(a[1]), "r"(a[2]), "r"(a[3]), "r"(b[0]), "r"(b[1]));
}

// ---------------- fp16 tensor GEMM: C[M,N] = A[M,K] @ BT[N,K]^T (fp16 out) -----------
#define BM 128
#define BN 64
#define BKH 32
#define HS 40           // smem stride in halfs (32 + 8 pad)

__global__ __launch_bounds__(256) void hgemm_kernel(
    const __half* __restrict__ A, const __half* __restrict__ BT,
    __half* __restrict__ C, int M, int N, int K)
{
    __shared__ __half Ah[2][BM][HS];
    __shared__ __half Bh[2][BN][HS];

    const int tid = threadIdx.x;
    const int lane = tid & 31;
    const int warp = tid >> 5;
    const int warp_m = warp & 3;
    const int warp_n = warp >> 2;
    const int g = lane >> 2;
    const int t = lane & 3;

    const int brow = blockIdx.y * BM;
    const int bcol = blockIdx.x * BN;

    float c[2][4][4];
    #pragma unroll
    for (int mi = 0; mi < 2; mi++)
        #pragma unroll
        for (int ni = 0; ni < 4; ni++)
            #pragma unroll
            for (int r = 0; r < 4; r++) c[mi][ni][r] = 0.f;

    const int a_r0 = tid >> 2;
    const int a_q = (tid & 3) * 8;
    const int b_r = tid >> 2;
    const int b_q = (tid & 3) * 8;

    {
        #pragma unroll
        for (int i = 0; i < 2; i++) {
            int r = a_r0 + i * 64;
            int gr = brow + r;
            int sz = (gr < M) ? 16 : 0;
            if (gr >= M) gr = 0;
            cp_async16(&Ah[0][r][a_q], &A[(long)gr * K + a_q], sz);
        }
        cp_async16(&Bh[0][b_r][b_q], &BT[(long)(bcol + b_r) * K + b_q], 16);
        cp_commit();
    }

    const int nk = K / BKH;
    int buf = 0;
    for (int tt = 0; tt < nk; tt++) {
        cp_wait0();
        __syncthreads();

        if (tt + 1 < nk) {
            int k0 = (tt + 1) * BKH;
            #pragma unroll
            for (int i = 0; i < 2; i++) {
                int r = a_r0 + i * 64;
                int gr = brow + r;
                int sz = (gr < M) ? 16 : 0;
                if (gr >= M) gr = 0;
                cp_async16(&Ah[buf ^ 1][r][a_q], &A[(long)gr * K + k0 + a_q], sz);
            }
            cp_async16(&Bh[buf ^ 1][b_r][b_q], &BT[(long)(bcol + b_r) * K + k0 + b_q], 16);
            cp_commit();
        }

        #pragma unroll
        for (int kk = 0; kk < BKH / 16; kk++) {
            const int ko = kk * 16;
            uint32_t a[2][4], b[4][2];
            #pragma unroll
            for (int mi = 0; mi < 2; mi++) {
                int row = warp_m * 32 + mi * 16 + g;
                a[mi][0] = *(const uint32_t*)&Ah[buf][row][ko + 2 * t];
                a[mi][1] = *(const uint32_t*)&Ah[buf][row + 8][ko + 2 * t];
                a[mi][2] = *(const uint32_t*)&Ah[buf][row][ko + 2 * t + 8];
                a[mi][3] = *(const uint32_t*)&Ah[buf][row + 8][ko + 2 * t + 8];
            }
            #pragma unroll
            for (int ni = 0; ni < 4; ni++) {
                int col = warp_n * 32 + ni * 8 + g;
                b[ni][0] = *(const uint32_t*)&Bh[buf][col][ko + 2 * t];
                b[ni][1] = *(const uint32_t*)&Bh[buf][col][ko + 2 * t + 8];
            }
            #pragma unroll
            for (int mi = 0; mi < 2; mi++)
                #pragma unroll
                for (int ni = 0; ni < 4; ni++)
                    mma_f16(c[mi][ni], a[mi], b[ni]);
        }
        buf ^= 1;
    }

    #pragma unroll
    for (int mi = 0; mi < 2; mi++) {
        int row0 = brow + warp_m * 32 + mi * 16 + g;
        int row1 = row0 + 8;
        #pragma unroll
        for (int ni = 0; ni < 4; ni++) {
            int col = bcol + warp_n * 32 + ni * 8 + t * 2;
            if (row0 < M) {
                __half2 v = __float22half2_rn(make_float2(c[mi][ni][0], c[mi][ni][1]));
                *(__half2*)&C[(long)row0 * N + col] = v;
            }
            if (row1 < M) {
                __half2 v = __float22half2_rn(make_float2(c[mi][ni][2], c[mi][ni][3]));
                *(__half2*)&C[(long)row1 * N + col] = v;
            }
        }
    }
}

// ---------------- fused pre-pass conversions ----------------
__global__ void cvt_kernel(const float* __restrict__ x, const float* __restrict__ W1,
                           const float* __restrict__ W2)
{
    int t = blockIdx.x * blockDim.x + threadIdx.x;
    int nx = NN * IND / 2;
    if (t < nx) {
        float2 v = ((const float2*)x)[t];
        ((__half2*)g_xh)[t] = __float22half2_rn(v);
    }
    if (t < F1 * IND) {
        int n = t / IND, k = t % IND;
        g_w1t[t] = __float2half_rn(W1[k * F1 + n]);
    }
    if (t < DOUT * F1) {
        int n = t / F1, k = t % F1;
        g_w2t[t] = __float2half_rn(W2[k * DOUT + n]);
    }
}

// ---------------- CSR build ----------------
__global__ void hist_kernel(const int* __restrict__ dst)
{
    int e = blockIdx.x * blockDim.x + threadIdx.x;
    if (e < NE) atomicAdd(&g_cnt[dst[e]], 1);
}

__global__ __launch_bounds__(1024) void scan_kernel()
{
    __shared__ int sums[1024];
    const int t = threadIdx.x;
    const int CH = (NN + 1023) / 1024;
    int lo = t * CH, hi = min(lo + CH, NN);
    int s = 0;
    for (int i = lo; i < hi; i++) s += g_cnt[i];
    sums[t] = s;
    __syncthreads();
    for (int off = 1; off < 1024; off <<= 1) {
        int v = (t >= off) ? sums[t - off] : 0;
        __syncthreads();
        sums[t] += v;
        __syncthreads();
    }
    int run = (t == 0) ? 0 : sums[t - 1];
    for (int i = lo; i < hi; i++) {
        int c = g_cnt[i];
        g_off[i] = run;
        g_cur[i] = run;
        g_cnt[i] = 0;
        run += c;
    }
    if (t == 0) g_off[NN] = NE;
}

__global__ void build_csr_kernel(const int* __restrict__ src, const int* __restrict__ dst)
{
    int e = blockIdx.x * blockDim.x + threadIdx.x;
    if (e >= NE) return;
    int pos = atomicAdd(&g_cur[dst[e]], 1);
    g_csr_src[pos] = src[e];
}

// ---------------- layer 1: el/er per (node, head), fp16 features ----------------
__global__ void elr1_kernel(const float* __restrict__ al, const float* __restrict__ ar)
{
    int t = blockIdx.x * blockDim.x + threadIdx.x;
    if (t >= NN * HEADS) return;
    int n = t >> 2, h = t & 3;
    const __half2* f = (const __half2*)&g_feat1h[n * F1 + h * HID];
    const float2* a = (const float2*)&al[h * HID];
    const float2* b = (const float2*)&ar[h * HID];
    float el = 0.f, er = 0.f;
    #pragma unroll
    for (int i = 0; i < HID / 2; i++) {
        float2 fv = __half22float2(f[i]);
        float2 av = a[i], bv = b[i];
        el += fv.x * av.x + fv.y * av.y;
        er += fv.x * bv.x + fv.y * bv.y;
    }
    g_el1[t] = el;
    g_er1[t] = er;
}

// ---------------- layer 1: fused softmax + fp16 gather-agg + elu (unroll-4) ----------
__global__ __launch_bounds__(256) void agg1_kernel()
{
    int d = (blockIdx.x * blockDim.x + threadIdx.x) >> 5;
    int lane = threadIdx.x & 31;
    if (d >= NN) return;
    const int lo = g_off[d], deg = g_off[d + 1] - lo;
    const int h = lane >> 3;
    const int fo = lane * 8;

    const float er = g_er1[d * 4 + h];

    float acc0[8] = {};
    float acc1[8] = {};
    float wsum = 0.f;

    int j = 0;
    for (; j + 4 <= deg; j += 4) {
        int s0 = g_csr_src[lo + j + 0];
        int s1 = g_csr_src[lo + j + 1];
        int s2 = g_csr_src[lo + j + 2];
        int s3 = g_csr_src[lo + j + 3];
        float el0 = g_el1[s0 * 4 + h];
        float el1 = g_el1[s1 * 4 + h];
        float el2 = g_el1[s2 * 4 + h];
        float el3 = g_el1[s3 * 4 + h];
        uint4 r0 = *(const uint4*)&g_feat1h[s0 * F1 + fo];
        uint4 r1 = *(const uint4*)&g_feat1h[s1 * F1 + fo];
        uint4 r2 = *(const uint4*)&g_feat1h[s2 * F1 + fo];
        uint4 r3 = *(const uint4*)&g_feat1h[s3 * F1 + fo];
        float w0 = __expf(lrelu(el0 + er));
        float w1 = __expf(lrelu(el1 + er));
        float w2 = __expf(lrelu(el2 + er));
        float w3 = __expf(lrelu(el3 + er));
        wsum += (w0 + w1) + (w2 + w3);
        const uint32_t* p0 = &r0.x;
        const uint32_t* p1 = &r1.x;
        const uint32_t* p2 = &r2.x;
        const uint32_t* p3 = &r3.x;
        #pragma unroll
        for (int q = 0; q < 4; q++) {
            float2 f0 = __half22float2(*(const __half2*)&p0[q]);
            float2 f1 = __half22float2(*(const __half2*)&p1[q]);
            float2 f2 = __half22float2(*(const __half2*)&p2[q]);
            float2 f3 = __half22float2(*(const __half2*)&p3[q]);
            acc0[q * 2 + 0] = fmaf(w0, f0.x, acc0[q * 2 + 0]);
            acc0[q * 2 + 1] = fmaf(w0, f0.y, acc0[q * 2 + 1]);
            acc1[q * 2 + 0] = fmaf(w1, f1.x, acc1[q * 2 + 0]);
            acc1[q * 2 + 1] = fmaf(w1, f1.y, acc1[q * 2 + 1]);
            acc0[q * 2 + 0] = fmaf(w2, f2.x, acc0[q * 2 + 0]);
            acc0[q * 2 + 1] = fmaf(w2, f2.y, acc0[q * 2 + 1]);
            acc1[q * 2 + 0] = fmaf(w3, f3.x, acc1[q * 2 + 0]);
            acc1[q * 2 + 1] = fmaf(w3, f3.y, acc1[q * 2 + 1]);
        }
    }
    for (; j < deg; j++) {
        int s = g_csr_src[lo + j];
        float w = __expf(lrelu(g_el1[s * 4 + h] + er));
        wsum += w;
        uint4 r = *(const uint4*)&g_feat1h[s * F1 + fo];
        const uint32_t* p = &r.x;
        #pragma unroll
        for (int q = 0; q < 4; q++) {
            float2 f = __half22float2(*(const __half2*)&p[q]);
            acc0[q * 2 + 0] = fmaf(w, f.x, acc0[q * 2 + 0]);
            acc0[q * 2 + 1] = fmaf(w, f.y, acc0[q * 2 + 1]);
        }
    }
    float inv = (deg > 0) ? (1.f / wsum) : 0.f;
    uint4 outp;
    uint32_t* po = &outp.x;
    #pragma unroll
    for (int q = 0; q < 4; q++) {
        float v0 = (acc0[q * 2 + 0] + acc1[q * 2 + 0]) * inv;
        float v1 = (acc0[q * 2 + 1] + acc1[q * 2 + 1]) * inv;
        v0 = v0 > 0.f ? v0 : expm1f(v0);
        v1 = v1 > 0.f ? v1 : expm1f(v1);
        __half2 hv = __float22half2_rn(make_float2(v0, v1));
        po[q] = *(uint32_t*)&hv;
    }
    *(uint4*)&g_h1h[d * F1 + fo] = outp;
}

// ---------------- layer 2: el/er per node, fp16 features ----------------
__global__ void elr2_kernel(const float* __restrict__ al, const float* __restrict__ ar)
{
    int n = blockIdx.x * blockDim.x + threadIdx.x;
    if (n >= NN) return;
    const __half2* f = (const __half2*)&g_feat2h[n * DOUT];
    const float2* a = (const float2*)al;
    const float2* b = (const float2*)ar;
    float el = 0.f, er = 0.f;
    #pragma unroll
    for (int i = 0; i < DOUT / 2; i++) {
        float2 fv = __half22float2(f[i]);
        float2 av = a[i], bv = b[i];
        el += fv.x * av.x + fv.y * av.y;
        er += fv.x * bv.x + fv.y * bv.y;
    }
    g_el2[n] = el;
    g_er2[n] = er;
}

// ---------------- layer 2: fused softmax + fp16 gather-agg -> out (unroll-8) ----------
__global__ __launch_bounds__(256) void agg2_kernel(float* __restrict__ out)
{
    int d = (blockIdx.x * blockDim.x + threadIdx.x) >> 5;
    int lane = threadIdx.x & 31;
    if (d >= NN) return;
    const int lo = g_off[d], deg = g_off[d + 1] - lo;

    const float er = g_er2[d];

    float a0 = 0.f, a1 = 0.f, b0 = 0.f, b1 = 0.f, wsum = 0.f;
    int j = 0;
    for (; j + 8 <= deg; j += 8) {
        int s[8];
        #pragma unroll
        for (int q = 0; q < 8; q++) s[q] = g_csr_src[lo + j + q];
        float e[8];
        #pragma unroll
        for (int q = 0; q < 8; q++) e[q] = g_el2[s[q]];
        float2 f[8];
        #pragma unroll
        for (int q = 0; q < 8; q++)
            f[q] = __half22float2(*(const __half2*)&g_feat2h[s[q] * DOUT + lane * 2]);
        float w[8];
        #pragma unroll
        for (int q = 0; q < 8; q++) w[q] = __expf(lrelu(e[q] + er));
        #pragma unroll
        for (int q = 0; q < 8; q++) wsum += w[q];
        #pragma unroll
        for (int q = 0; q < 8; q += 2) {
            a0 = fmaf(w[q], f[q].x, a0);     a1 = fmaf(w[q], f[q].y, a1);
            b0 = fmaf(w[q + 1], f[q + 1].x, b0); b1 = fmaf(w[q + 1], f[q + 1].y, b1);
        }
    }
    for (; j < deg; j++) {
        int s = g_csr_src[lo + j];
        float w = __expf(lrelu(g_el2[s] + er));
        wsum += w;
        float2 f = __half22float2(*(const __half2*)&g_feat2h[s * DOUT + lane * 2]);
        a0 = fmaf(w, f.x, a0); a1 = fmaf(w, f.y, a1);
    }
    float inv = (deg > 0) ? (1.f / wsum) : 0.f;
    *(float2*)&out[d * DOUT + lane * 2] = make_float2((a0 + b0) * inv, (a1 + b1) * inv);
}

// ---------------- launch ----------------
extern "C" void kernel_launch(void* const* d_in, const int* in_sizes, int n_in,
                              void* d_out, int out_size)
{
    const float* x   = (const float*)d_in[0];
    const int*   src = (const int*)d_in[1];
    const int*   dst = (const int*)d_in[2];
    const float* W1  = (const float*)d_in[3];
    const float* al1 = (const float*)d_in[4];
    const float* ar1 = (const float*)d_in[5];
    const float* W2  = (const float*)d_in[6];
    const float* al2 = (const float*)d_in[7];
    const float* ar2 = (const float*)d_in[8];
    float* out = (float*)d_out;

    void *p_xh, *p_w1t, *p_w2t, *p_feat1h, *p_h1h, *p_feat2h;
    cudaGetSymbolAddress(&p_xh, g_xh);
    cudaGetSymbolAddress(&p_w1t, g_w1t);
    cudaGetSymbolAddress(&p_w2t, g_w2t);
    cudaGetSymbolAddress(&p_feat1h, g_feat1h);
    cudaGetSymbolAddress(&p_h1h, g_h1h);
    cudaGetSymbolAddress(&p_feat2h, g_feat2h);

    // Side stream + events for a parallel CSR branch in the captured graph.
    // Host-side objects only (no device memory); created once and cached.
    static cudaStream_t sA = nullptr;
    static cudaEvent_t evFork = nullptr, evJoin = nullptr;
    if (sA == nullptr) {
        cudaStreamCreateWithFlags(&sA, cudaStreamNonBlocking);
        cudaEventCreateWithFlags(&evFork, cudaEventDisableTiming);
        cudaEventCreateWithFlags(&evJoin, cudaEventDisableTiming);
    }

    // ---- fork: CSR build chain on side stream ----
    cudaEventRecord(evFork, 0);
    cudaStreamWaitEvent(sA, evFork, 0);
    hist_kernel<<<(NE + 255) / 256, 256, 0, sA>>>(dst);
    scan_kernel<<<1, 1024, 0, sA>>>();
    build_csr_kernel<<<(NE + 255) / 256, 256, 0, sA>>>(src, dst);
    cudaEventRecord(evJoin, sA);

    // ---- main stream: conversions + layer-1 GEMM + el/er ----
    cvt_kernel<<<(NN * IND / 2 + 255) / 256, 256>>>(x, W1, W2);
    {
        dim3 grid(F1 / BN, (NN + BM - 1) / BM);
        hgemm_kernel<<<grid, 256>>>((const __half*)p_xh, (const __half*)p_w1t,
                                    (__half*)p_feat1h, NN, F1, IND);
    }
    elr1_kernel<<<(NN * HEADS + 255) / 256, 256>>>(al1, ar1);

    // ---- join: CSR must be ready before aggregation ----
    cudaStreamWaitEvent(0, evJoin, 0);

    agg1_kernel<<<(NN * 32 + 255) / 256, 256>>>();

    // ---- layer 2 ----
    {
        dim3 grid(DOUT / BN, (NN + BM - 1) / BM);
        hgemm_kernel<<<grid, 256>>>((const __half*)p_h1h, (const __half*)p_w2t,
                                    (__half*)p_feat2h, NN, DOUT, F1);
    }
    elr2_kernel<<<(NN + 255) / 256, 256>>>(al2, ar2);
    agg2_kernel<<<(NN * 32 + 255) / 256, 256>>>(out);
}